// round 1
// baseline (speedup 1.0000x reference)
#include <cuda_runtime.h>
#include <math.h>

// ---------------- problem constants ----------------
// B=4, S=256, E=512, H=8, HD=64, F=2048, L=4, V=32000
#define N_ROWS   1024        // B*S
#define E_DIM    512
#define QKV_DIM  1536
#define FF_DIM   2048
#define V_DIM    32000
#define N_BH     32          // B*H
#define S_LEN    256

// ---------------- scratch (device globals; no runtime allocation) ----------------
__device__ float g_x  [N_ROWS * E_DIM];        // residual stream
__device__ float g_h  [N_ROWS * E_DIM];        // layernorm output
__device__ float g_qkv[N_ROWS * QKV_DIM];      // fused qkv
__device__ float g_qk [N_BH * S_LEN * S_LEN];  // scores -> probs (in place)
__device__ float g_qr [N_BH * S_LEN * 512];    // rel-pos bias table QR^T (511 used cols, ld=512)
__device__ float g_o  [N_ROWS * E_DIM];        // attention output
__device__ float g_g  [N_ROWS * FF_DIM];       // gelu(ff1)

// ---------------- reductions ----------------
__device__ __forceinline__ float warpSum(float v) {
    #pragma unroll
    for (int o = 16; o; o >>= 1) v += __shfl_xor_sync(0xffffffffu, v, o);
    return v;
}
__device__ __forceinline__ float warpMax(float v) {
    #pragma unroll
    for (int o = 16; o; o >>= 1) v = fmaxf(v, __shfl_xor_sync(0xffffffffu, v, o));
    return v;
}
// blockDim.x == 256 (8 warps) assumed
__device__ __forceinline__ float blockSum(float v) {
    __shared__ float sm[8];
    int lane = threadIdx.x & 31, w = threadIdx.x >> 5;
    v = warpSum(v);
    __syncthreads();                 // protect sm from previous use
    if (lane == 0) sm[w] = v;
    __syncthreads();
    float r = 0.f;
    #pragma unroll
    for (int i = 0; i < 8; i++) r += sm[i];
    return r;
}
__device__ __forceinline__ float blockMax(float v) {
    __shared__ float sm[8];
    int lane = threadIdx.x & 31, w = threadIdx.x >> 5;
    v = warpMax(v);
    __syncthreads();
    if (lane == 0) sm[w] = v;
    __syncthreads();
    float r = -3.4e38f;
    #pragma unroll
    for (int i = 0; i < 8; i++) r = fmaxf(r, sm[i]);
    return r;
}

// ---------------- embed + input layernorm (block per row, 256 thr) ----------------
__global__ void embed_ln_k(const int* __restrict__ src, const float* __restrict__ emb,
                           const float* __restrict__ s, const float* __restrict__ b,
                           float* __restrict__ out) {
    int row = blockIdx.x, t = threadIdx.x;
    int tok = src[row];
    const float SC = 22.62741699796952f;  // sqrt(512)
    float v0 = emb[(size_t)tok * E_DIM + t]       * SC;
    float v1 = emb[(size_t)tok * E_DIM + t + 256] * SC;
    float mean = blockSum(v0 + v1) * (1.f / E_DIM);
    float d0 = v0 - mean, d1 = v1 - mean;
    float var = blockSum(d0 * d0 + d1 * d1) * (1.f / E_DIM);
    float r = rsqrtf(var + 1e-5f);
    out[(size_t)row * E_DIM + t]       = d0 * r * s[t]       + b[t];
    out[(size_t)row * E_DIM + t + 256] = d1 * r * s[t + 256] + b[t + 256];
}

// ---------------- layernorm over E=512 (block per row, 256 thr) ----------------
__global__ void layernorm_k(const float* __restrict__ in, const float* __restrict__ s,
                            const float* __restrict__ b, float* __restrict__ out) {
    int row = blockIdx.x, t = threadIdx.x;
    float v0 = in[(size_t)row * E_DIM + t];
    float v1 = in[(size_t)row * E_DIM + t + 256];
    float mean = blockSum(v0 + v1) * (1.f / E_DIM);
    float d0 = v0 - mean, d1 = v1 - mean;
    float var = blockSum(d0 * d0 + d1 * d1) * (1.f / E_DIM);
    float r = rsqrtf(var + 1e-5f);
    out[(size_t)row * E_DIM + t]       = d0 * r * s[t]       + b[t];
    out[(size_t)row * E_DIM + t + 256] = d1 * r * s[t + 256] + b[t + 256];
}

// ---------------- fused scale + rel-bias + mask + softmax ----------------
// grid (S, 32), 256 threads; qk updated in place to probabilities
__global__ void softmax_k(float* __restrict__ qk, const float* __restrict__ qr) {
    int bh = blockIdx.y, l = blockIdx.x, m = threadIdx.x;
    float* row = qk + (size_t)bh * (S_LEN * S_LEN) + (size_t)l * S_LEN;
    float bias = qr[(size_t)bh * (S_LEN * 512) + (size_t)l * 512 + (m - l + 255)];
    float v = row[m] * 0.125f + bias + ((m > l) ? 1.0f : 0.0f);
    float mx = blockMax(v);
    float e = expf(v - mx);
    float sum = blockSum(e);
    row[m] = e / sum;
}

// ---------------- generic 128x128x8 SGEMM ----------------
// C[i,j] = epi( sum_k A[i,k]*B(k,j) + bias[j] ), optionally batched over blockIdx.z
// BLAY==0: B is [N,K] k-contiguous (NT, i.e. C = A @ B^T)   BLAY==1: B is [K,N] (NN)
// EPI: 0 = bias only, 1 = residual add into C, 2 = exact GELU
// Per-batch offsets are decomposed z -> (zb = z/8, zh = z%8).
// Requirements: M % 128 == 0, K % 8 == 0 (N may be ragged).
template<int EPI, int BLAY>
__global__ __launch_bounds__(256)
void gemm_k(const float* __restrict__ A, const float* __restrict__ B,
            const float* __restrict__ bias, float* __restrict__ C,
            int M, int N, int K, int lda, int ldb, int ldc,
            int aOffB, int aOffH, int bOffB, int bOffH, int cOffB, int cOffH) {
    __shared__ float As[8][128];
    __shared__ float Bs[8][128];

    int z = blockIdx.z;
    int zb = z >> 3, zh = z & 7;
    A += (size_t)zb * aOffB + (size_t)zh * aOffH;
    B += (size_t)zb * bOffB + (size_t)zh * bOffH;
    C += (size_t)zb * cOffB + (size_t)zh * cOffH;

    int tid = threadIdx.x;
    int tx = tid & 15, ty = tid >> 4;
    int row0 = blockIdx.y * 128, col0 = blockIdx.x * 128;

    float acc[8][8];
    #pragma unroll
    for (int i = 0; i < 8; i++)
        #pragma unroll
        for (int j = 0; j < 8; j++) acc[i][j] = 0.f;

    int arow = tid >> 1;            // 0..127
    int ak   = (tid & 1) * 4;       // 0 or 4
    int bk8  = tid >> 5;            // 0..7   (NN)
    int bc   = (tid & 31) * 4;      // 0..124 (NN)

    for (int k0 = 0; k0 < K; k0 += 8) {
        const float* Ap = A + (size_t)(row0 + arow) * lda + k0 + ak;
        #pragma unroll
        for (int i = 0; i < 4; i++) As[ak + i][arow] = Ap[i];

        if (BLAY == 0) {
            int j = col0 + arow;
            const float* Bp = B + (size_t)j * ldb + k0 + ak;
            #pragma unroll
            for (int i = 0; i < 4; i++) Bs[ak + i][arow] = (j < N) ? Bp[i] : 0.f;
        } else {
            const float* Bp = B + (size_t)(k0 + bk8) * ldb + col0 + bc;
            #pragma unroll
            for (int i = 0; i < 4; i++) {
                int j = col0 + bc + i;
                Bs[bk8][bc + i] = (j < N) ? Bp[i] : 0.f;
            }
        }
        __syncthreads();

        #pragma unroll
        for (int k = 0; k < 8; k++) {
            float a[8], bb[8];
            #pragma unroll
            for (int i = 0; i < 8; i++) a[i] = As[k][ty * 8 + i];
            #pragma unroll
            for (int j = 0; j < 8; j++) bb[j] = Bs[k][tx * 8 + j];
            #pragma unroll
            for (int i = 0; i < 8; i++)
                #pragma unroll
                for (int j = 0; j < 8; j++) acc[i][j] = fmaf(a[i], bb[j], acc[i][j]);
        }
        __syncthreads();
    }

    #pragma unroll
    for (int i = 0; i < 8; i++) {
        int r = row0 + ty * 8 + i;
        #pragma unroll
        for (int j = 0; j < 8; j++) {
            int c = col0 + tx * 8 + j;
            if (c < N) {
                float v = acc[i][j];
                if (bias) v += bias[c];
                size_t idx = (size_t)r * ldc + c;
                if (EPI == 1) v += C[idx];
                if (EPI == 2) v = 0.5f * v * (1.f + erff(v * 0.7071067811865476f));
                C[idx] = v;
            }
        }
    }
}

// ---------------- driver ----------------
extern "C" void kernel_launch(void* const* d_in, const int* in_sizes, int n_in,
                              void* d_out, int out_size) {
    const int*   src   = (const int*)  d_in[0];
    const float* emb   = (const float*)d_in[1];
    const float* rel   = (const float*)d_in[2];
    const float* nin_s = (const float*)d_in[3];
    const float* nin_b = (const float*)d_in[4];
    const float* inW   = (const float*)d_in[5];
    const float* inB   = (const float*)d_in[6];
    const float* outW  = (const float*)d_in[7];
    const float* outB  = (const float*)d_in[8];
    const float* ln1s  = (const float*)d_in[9];
    const float* ln1b  = (const float*)d_in[10];
    const float* ln2s  = (const float*)d_in[11];
    const float* ln2b  = (const float*)d_in[12];
    const float* w1    = (const float*)d_in[13];
    const float* b1    = (const float*)d_in[14];
    const float* w2    = (const float*)d_in[15];
    const float* b2    = (const float*)d_in[16];
    const float* nfs   = (const float*)d_in[17];
    const float* nfb   = (const float*)d_in[18];
    const float* decW  = (const float*)d_in[19];
    const float* decB  = (const float*)d_in[20];
    float* out = (float*)d_out;

    float *x, *h, *qkv, *qk, *qr, *o, *g;
    cudaGetSymbolAddress((void**)&x,   g_x);
    cudaGetSymbolAddress((void**)&h,   g_h);
    cudaGetSymbolAddress((void**)&qkv, g_qkv);
    cudaGetSymbolAddress((void**)&qk,  g_qk);
    cudaGetSymbolAddress((void**)&qr,  g_qr);
    cudaGetSymbolAddress((void**)&o,   g_o);
    cudaGetSymbolAddress((void**)&g,   g_g);

    // x = LN(emb[src] * sqrt(E))
    embed_ln_k<<<N_ROWS, 256>>>(src, emb, nin_s, nin_b, x);

    for (int l = 0; l < 4; l++) {
        const float* inW_l  = inW  + (size_t)l * QKV_DIM * E_DIM;
        const float* inB_l  = inB  + (size_t)l * QKV_DIM;
        const float* outW_l = outW + (size_t)l * E_DIM * E_DIM;
        const float* outB_l = outB + (size_t)l * E_DIM;
        const float* w1_l   = w1   + (size_t)l * FF_DIM * E_DIM;
        const float* b1_l   = b1   + (size_t)l * FF_DIM;
        const float* w2_l   = w2   + (size_t)l * E_DIM * FF_DIM;
        const float* b2_l   = b2   + (size_t)l * E_DIM;

        // h = LN1(x)
        layernorm_k<<<N_ROWS, 256>>>(x, ln1s + l * E_DIM, ln1b + l * E_DIM, h);

        // qkv = h @ inW^T + inB   [1024 x 1536]
        gemm_k<0, 0><<<dim3(12, 8, 1), 256>>>(h, inW_l, inB_l, qkv,
            N_ROWS, QKV_DIM, E_DIM, E_DIM, E_DIM, QKV_DIM, 0, 0, 0, 0, 0, 0);

        // scores[bh] = Q @ K^T   (batched over z = b*8 + h), unscaled
        gemm_k<0, 0><<<dim3(2, 2, N_BH), 256>>>(qkv, qkv + E_DIM, (const float*)0, qk,
            S_LEN, S_LEN, 64, QKV_DIM, QKV_DIM, S_LEN,
            S_LEN * QKV_DIM, 64,            // A: Q  (b-stride, h-stride)
            S_LEN * QKV_DIM, 64,            // B: K
            8 * S_LEN * S_LEN, S_LEN * S_LEN);

        // qr[bh] = Q @ R^T  with R[p,d] = rel_table[p, h*64+d], p in [0,511)
        gemm_k<0, 0><<<dim3(4, 2, N_BH), 256>>>(qkv, rel, (const float*)0, qr,
            S_LEN, 511, 64, QKV_DIM, E_DIM, 512,
            S_LEN * QKV_DIM, 64,
            0, 64,
            8 * S_LEN * 512, S_LEN * 512);

        // probs = softmax(scores/8 + qr_gather + triu_one_mask)
        softmax_k<<<dim3(S_LEN, N_BH), 256>>>(qk, qr);

        // o[bh] = probs @ V   (NN)
        gemm_k<0, 1><<<dim3(1, 2, N_BH), 256>>>(qk, qkv + 2 * E_DIM, (const float*)0, o,
            S_LEN, 64, S_LEN, S_LEN, QKV_DIM, E_DIM,
            8 * S_LEN * S_LEN, S_LEN * S_LEN,
            S_LEN * QKV_DIM, 64,
            S_LEN * E_DIM, 64);

        // x += o @ outW^T + outB
        gemm_k<1, 0><<<dim3(4, 8, 1), 256>>>(o, outW_l, outB_l, x,
            N_ROWS, E_DIM, E_DIM, E_DIM, E_DIM, E_DIM, 0, 0, 0, 0, 0, 0);

        // h = LN2(x)
        layernorm_k<<<N_ROWS, 256>>>(x, ln2s + l * E_DIM, ln2b + l * E_DIM, h);

        // g = gelu(h @ w1^T + b1)   [1024 x 2048]
        gemm_k<2, 0><<<dim3(16, 8, 1), 256>>>(h, w1_l, b1_l, g,
            N_ROWS, FF_DIM, E_DIM, E_DIM, E_DIM, FF_DIM, 0, 0, 0, 0, 0, 0);

        // x += g @ w2^T + b2
        gemm_k<1, 0><<<dim3(4, 8, 1), 256>>>(g, w2_l, b2_l, x,
            N_ROWS, E_DIM, FF_DIM, FF_DIM, FF_DIM, E_DIM, 0, 0, 0, 0, 0, 0);
    }

    // h = LN_final(x)
    layernorm_k<<<N_ROWS, 256>>>(x, nfs, nfb, h);

    // out = h @ dec_w^T + dec_b   [1024 x 32000]
    gemm_k<0, 0><<<dim3(250, 8, 1), 256>>>(h, decW, decB, out,
        N_ROWS, V_DIM, E_DIM, E_DIM, E_DIM, V_DIM, 0, 0, 0, 0, 0, 0);
}

// round 2
// speedup vs baseline: 2.2795x; 2.2795x over previous
#include <cuda_runtime.h>
#include <math.h>
#include <stdint.h>

// ---------------- problem constants ----------------
// B=4, S=256, E=512, H=8, HD=64, F=2048, L=4, V=32000
#define N_ROWS   1024        // B*S
#define E_DIM    512
#define QKV_DIM  1536
#define FF_DIM   2048
#define V_DIM    32000
#define N_BH     32          // B*H
#define S_LEN    256

// ---------------- scratch (device globals; no runtime allocation) ----------------
__device__ float g_x  [N_ROWS * E_DIM];        // residual stream
__device__ float g_h  [N_ROWS * E_DIM];        // layernorm output
__device__ float g_qkv[N_ROWS * QKV_DIM];      // fused qkv
__device__ float g_qk [N_BH * S_LEN * S_LEN];  // scores -> probs (in place)
__device__ float g_qr [N_BH * S_LEN * 512];    // rel-pos bias QR^T (511 used cols, ld=512)
__device__ float g_o  [N_ROWS * E_DIM];        // attention output
__device__ float g_g  [N_ROWS * FF_DIM];       // gelu(ff1)

// ---------------- reductions ----------------
__device__ __forceinline__ float warpSum(float v) {
    #pragma unroll
    for (int o = 16; o; o >>= 1) v += __shfl_xor_sync(0xffffffffu, v, o);
    return v;
}
__device__ __forceinline__ float warpMax(float v) {
    #pragma unroll
    for (int o = 16; o; o >>= 1) v = fmaxf(v, __shfl_xor_sync(0xffffffffu, v, o));
    return v;
}
__device__ __forceinline__ float blockSum(float v) {
    __shared__ float sm[8];
    int lane = threadIdx.x & 31, w = threadIdx.x >> 5;
    v = warpSum(v);
    __syncthreads();
    if (lane == 0) sm[w] = v;
    __syncthreads();
    float r = 0.f;
    #pragma unroll
    for (int i = 0; i < 8; i++) r += sm[i];
    return r;
}
__device__ __forceinline__ float blockMax(float v) {
    __shared__ float sm[8];
    int lane = threadIdx.x & 31, w = threadIdx.x >> 5;
    v = warpMax(v);
    __syncthreads();
    if (lane == 0) sm[w] = v;
    __syncthreads();
    float r = -3.4e38f;
    #pragma unroll
    for (int i = 0; i < 8; i++) r = fmaxf(r, sm[i]);
    return r;
}

// ---------------- embed + input layernorm (block per row, 256 thr) ----------------
__global__ void embed_ln_k(const int* __restrict__ src, const float* __restrict__ emb,
                           const float* __restrict__ s, const float* __restrict__ b,
                           float* __restrict__ out) {
    int row = blockIdx.x, t = threadIdx.x;
    int tok = src[row];
    const float SC = 22.62741699796952f;  // sqrt(512)
    float v0 = emb[(size_t)tok * E_DIM + t]       * SC;
    float v1 = emb[(size_t)tok * E_DIM + t + 256] * SC;
    float mean = blockSum(v0 + v1) * (1.f / E_DIM);
    float d0 = v0 - mean, d1 = v1 - mean;
    float var = blockSum(d0 * d0 + d1 * d1) * (1.f / E_DIM);
    float r = rsqrtf(var + 1e-5f);
    out[(size_t)row * E_DIM + t]       = d0 * r * s[t]       + b[t];
    out[(size_t)row * E_DIM + t + 256] = d1 * r * s[t + 256] + b[t + 256];
}

// ---------------- layernorm over E=512 (block per row, 256 thr) ----------------
__global__ void layernorm_k(const float* __restrict__ in, const float* __restrict__ s,
                            const float* __restrict__ b, float* __restrict__ out) {
    int row = blockIdx.x, t = threadIdx.x;
    float v0 = in[(size_t)row * E_DIM + t];
    float v1 = in[(size_t)row * E_DIM + t + 256];
    float mean = blockSum(v0 + v1) * (1.f / E_DIM);
    float d0 = v0 - mean, d1 = v1 - mean;
    float var = blockSum(d0 * d0 + d1 * d1) * (1.f / E_DIM);
    float r = rsqrtf(var + 1e-5f);
    out[(size_t)row * E_DIM + t]       = d0 * r * s[t]       + b[t];
    out[(size_t)row * E_DIM + t + 256] = d1 * r * s[t + 256] + b[t + 256];
}

// ---------------- fused scale + rel-bias + mask + softmax ----------------
__global__ void softmax_k(float* __restrict__ qk, const float* __restrict__ qr) {
    int bh = blockIdx.y, l = blockIdx.x, m = threadIdx.x;
    float* row = qk + (size_t)bh * (S_LEN * S_LEN) + (size_t)l * S_LEN;
    float bias = qr[(size_t)bh * (S_LEN * 512) + (size_t)l * 512 + (m - l + 255)];
    float v = row[m] * 0.125f + bias + ((m > l) ? 1.0f : 0.0f);
    float mx = blockMax(v);
    float e = expf(v - mx);
    float sum = blockSum(e);
    row[m] = e / sum;
}

// ---------------- tf32 helpers ----------------
__device__ __forceinline__ void split_tf32(float f, uint32_t& hi, uint32_t& lo) {
    asm("cvt.rna.tf32.f32 %0, %1;" : "=r"(hi) : "f"(f));
    float r = f - __uint_as_float(hi);
    asm("cvt.rna.tf32.f32 %0, %1;" : "=r"(lo) : "f"(r));
}

#define MMA_TF32(C, A0, A1, A2, A3, B0, B1)                                     \
    asm volatile("mma.sync.aligned.m16n8k8.row.col.f32.tf32.tf32.f32 "          \
                 "{%0,%1,%2,%3},{%4,%5,%6,%7},{%8,%9},{%0,%1,%2,%3};"           \
                 : "+f"(C[0]), "+f"(C[1]), "+f"(C[2]), "+f"(C[3])               \
                 : "r"(A0), "r"(A1), "r"(A2), "r"(A3), "r"(B0), "r"(B1))

__device__ __forceinline__ void cp16(float* dst, const float* src, bool pred) {
    uint32_t d = (uint32_t)__cvta_generic_to_shared(dst);
    int sz = pred ? 16 : 0;
    asm volatile("cp.async.cg.shared.global [%0], [%1], 16, %2;"
                 :: "r"(d), "l"(src), "r"(sz));
}

// ---------------- tensor-core 3xTF32 GEMM, 128x128 tiles ----------------
// C[i,j] = epi( sum_k A[i,k]*B(k,j) + bias[j] ), batched over blockIdx.z
// BLAY==0: B is [N,K] row-major (NT, C = A @ B^T)   BLAY==1: B is [K,N] (NN)
// EPI: 0 = bias only, 1 = residual add into C, 2 = exact GELU
// Requirements: M % 128 == 0, K % 16 == 0. N ragged OK (NN path needs N % 8 == 0).
template<int EPI, int BLAY>
__global__ __launch_bounds__(256)
void mma_gemm_k(const float* __restrict__ A, const float* __restrict__ B,
                const float* __restrict__ bias, float* __restrict__ C,
                int M, int N, int K, int lda, int ldb, int ldc,
                int aOffB, int aOffH, int bOffB, int bOffH, int cOffB, int cOffH) {
    constexpr int KPAD = 20;
    __shared__ float As[2][128 * KPAD];
    __shared__ float Bs[2][128 * KPAD];

    int z = blockIdx.z;
    int zb = z >> 3, zh = z & 7;
    A += (size_t)zb * aOffB + (size_t)zh * aOffH;
    B += (size_t)zb * bOffB + (size_t)zh * bOffH;
    C += (size_t)zb * cOffB + (size_t)zh * cOffH;

    int tid  = threadIdx.x;
    int lane = tid & 31, wid = tid >> 5;
    int wm0 = (wid >> 2) * 64;     // warp tile 64x32 in a 2x4 warp grid
    int wn0 = (wid & 3) * 32;
    int g   = lane >> 2;           // 0..7
    int tg  = lane & 3;            // 0..3
    int row0 = blockIdx.y * 128, col0 = blockIdx.x * 128;

    float acc[4][4][4] = {};       // [mi][ni][frag]

    // loader indices
    int lm = tid >> 1;             // 0..127
    int lk = (tid & 1) * 8;        // 0 or 8
    int nkr = tid >> 4;            // 0..15   (NN)
    int ntn = (tid & 15) * 8;      // 0..120  (NN)

    int nk = K >> 4;

    // ---- issue chunk 0 ----
    {
        const float* Ap = A + (size_t)(row0 + lm) * lda + lk;
        cp16(&As[0][lm * KPAD + lk],     Ap,     true);
        cp16(&As[0][lm * KPAD + lk + 4], Ap + 4, true);
        if (BLAY == 0) {
            bool p = (col0 + lm) < N;
            const float* Bp = B + (size_t)(col0 + lm) * ldb + lk;
            cp16(&Bs[0][lm * KPAD + lk],     Bp,     p);
            cp16(&Bs[0][lm * KPAD + lk + 4], Bp + 4, p);
        } else {
            const float* Bp = B + (size_t)nkr * ldb + col0 + ntn;
            float4 v0 = make_float4(0, 0, 0, 0), v1 = v0;
            if (col0 + ntn     < N) v0 = *(const float4*)(Bp);
            if (col0 + ntn + 4 < N) v1 = *(const float4*)(Bp + 4);
            Bs[0][(ntn + 0) * KPAD + nkr] = v0.x;
            Bs[0][(ntn + 1) * KPAD + nkr] = v0.y;
            Bs[0][(ntn + 2) * KPAD + nkr] = v0.z;
            Bs[0][(ntn + 3) * KPAD + nkr] = v0.w;
            Bs[0][(ntn + 4) * KPAD + nkr] = v1.x;
            Bs[0][(ntn + 5) * KPAD + nkr] = v1.y;
            Bs[0][(ntn + 6) * KPAD + nkr] = v1.z;
            Bs[0][(ntn + 7) * KPAD + nkr] = v1.w;
        }
    }
    asm volatile("cp.async.commit_group;");

    for (int i = 0; i < nk; i++) {
        int s = i & 1;
        // ---- prefetch chunk i+1 into the other buffer ----
        if (i + 1 < nk) {
            int k0 = (i + 1) << 4;
            int s2 = s ^ 1;
            const float* Ap = A + (size_t)(row0 + lm) * lda + k0 + lk;
            cp16(&As[s2][lm * KPAD + lk],     Ap,     true);
            cp16(&As[s2][lm * KPAD + lk + 4], Ap + 4, true);
            if (BLAY == 0) {
                bool p = (col0 + lm) < N;
                const float* Bp = B + (size_t)(col0 + lm) * ldb + k0 + lk;
                cp16(&Bs[s2][lm * KPAD + lk],     Bp,     p);
                cp16(&Bs[s2][lm * KPAD + lk + 4], Bp + 4, p);
            } else {
                const float* Bp = B + (size_t)(k0 + nkr) * ldb + col0 + ntn;
                float4 v0 = make_float4(0, 0, 0, 0), v1 = v0;
                if (col0 + ntn     < N) v0 = *(const float4*)(Bp);
                if (col0 + ntn + 4 < N) v1 = *(const float4*)(Bp + 4);
                Bs[s2][(ntn + 0) * KPAD + nkr] = v0.x;
                Bs[s2][(ntn + 1) * KPAD + nkr] = v0.y;
                Bs[s2][(ntn + 2) * KPAD + nkr] = v0.z;
                Bs[s2][(ntn + 3) * KPAD + nkr] = v0.w;
                Bs[s2][(ntn + 4) * KPAD + nkr] = v1.x;
                Bs[s2][(ntn + 5) * KPAD + nkr] = v1.y;
                Bs[s2][(ntn + 6) * KPAD + nkr] = v1.z;
                Bs[s2][(ntn + 7) * KPAD + nkr] = v1.w;
            }
        }
        asm volatile("cp.async.commit_group;");
        asm volatile("cp.async.wait_group 1;");
        __syncthreads();

        // ---- compute on buffer s ----
        const float* as = As[s];
        const float* bs = Bs[s];
        #pragma unroll
        for (int ks = 0; ks < 16; ks += 8) {
            uint32_t ahi[4][4], alo[4][4];
            #pragma unroll
            for (int mi = 0; mi < 4; mi++) {
                int mb = wm0 + mi * 16 + g;
                split_tf32(as[(mb)     * KPAD + ks + tg],     ahi[mi][0], alo[mi][0]);
                split_tf32(as[(mb + 8) * KPAD + ks + tg],     ahi[mi][1], alo[mi][1]);
                split_tf32(as[(mb)     * KPAD + ks + tg + 4], ahi[mi][2], alo[mi][2]);
                split_tf32(as[(mb + 8) * KPAD + ks + tg + 4], ahi[mi][3], alo[mi][3]);
            }
            uint32_t bhi[4][2], blo[4][2];
            #pragma unroll
            for (int ni = 0; ni < 4; ni++) {
                int nb = wn0 + ni * 8 + g;
                split_tf32(bs[nb * KPAD + ks + tg],     bhi[ni][0], blo[ni][0]);
                split_tf32(bs[nb * KPAD + ks + tg + 4], bhi[ni][1], blo[ni][1]);
            }
            #pragma unroll
            for (int mi = 0; mi < 4; mi++)
                #pragma unroll
                for (int ni = 0; ni < 4; ni++) {
                    MMA_TF32(acc[mi][ni], ahi[mi][0], ahi[mi][1], ahi[mi][2], ahi[mi][3],
                             bhi[ni][0], bhi[ni][1]);
                    MMA_TF32(acc[mi][ni], alo[mi][0], alo[mi][1], alo[mi][2], alo[mi][3],
                             bhi[ni][0], bhi[ni][1]);
                    MMA_TF32(acc[mi][ni], ahi[mi][0], ahi[mi][1], ahi[mi][2], ahi[mi][3],
                             blo[ni][0], blo[ni][1]);
                }
        }
        __syncthreads();
    }

    // ---- epilogue ----
    #pragma unroll
    for (int mi = 0; mi < 4; mi++) {
        #pragma unroll
        for (int rr = 0; rr < 2; rr++) {
            int r = row0 + wm0 + mi * 16 + g + rr * 8;
            float* Crow = C + (size_t)r * ldc;
            #pragma unroll
            for (int ni = 0; ni < 4; ni++) {
                int c = col0 + wn0 + ni * 8 + tg * 2;
                float v0 = acc[mi][ni][rr * 2];
                float v1 = acc[mi][ni][rr * 2 + 1];
                if (c + 1 < N) {
                    if (bias) { v0 += bias[c]; v1 += bias[c + 1]; }
                    if (EPI == 1) {
                        float2 old = *(const float2*)&Crow[c];
                        v0 += old.x; v1 += old.y;
                    }
                    if (EPI == 2) {
                        v0 = 0.5f * v0 * (1.f + erff(v0 * 0.7071067811865476f));
                        v1 = 0.5f * v1 * (1.f + erff(v1 * 0.7071067811865476f));
                    }
                    *(float2*)&Crow[c] = make_float2(v0, v1);
                } else if (c < N) {
                    if (bias) v0 += bias[c];
                    if (EPI == 1) v0 += Crow[c];
                    if (EPI == 2) v0 = 0.5f * v0 * (1.f + erff(v0 * 0.7071067811865476f));
                    Crow[c] = v0;
                }
            }
        }
    }
}

// ---------------- driver ----------------
extern "C" void kernel_launch(void* const* d_in, const int* in_sizes, int n_in,
                              void* d_out, int out_size) {
    const int*   src   = (const int*)  d_in[0];
    const float* emb   = (const float*)d_in[1];
    const float* rel   = (const float*)d_in[2];
    const float* nin_s = (const float*)d_in[3];
    const float* nin_b = (const float*)d_in[4];
    const float* inW   = (const float*)d_in[5];
    const float* inB   = (const float*)d_in[6];
    const float* outW  = (const float*)d_in[7];
    const float* outB  = (const float*)d_in[8];
    const float* ln1s  = (const float*)d_in[9];
    const float* ln1b  = (const float*)d_in[10];
    const float* ln2s  = (const float*)d_in[11];
    const float* ln2b  = (const float*)d_in[12];
    const float* w1    = (const float*)d_in[13];
    const float* b1    = (const float*)d_in[14];
    const float* w2    = (const float*)d_in[15];
    const float* b2    = (const float*)d_in[16];
    const float* nfs   = (const float*)d_in[17];
    const float* nfb   = (const float*)d_in[18];
    const float* decW  = (const float*)d_in[19];
    const float* decB  = (const float*)d_in[20];
    float* out = (float*)d_out;

    float *x, *h, *qkv, *qk, *qr, *o, *g;
    cudaGetSymbolAddress((void**)&x,   g_x);
    cudaGetSymbolAddress((void**)&h,   g_h);
    cudaGetSymbolAddress((void**)&qkv, g_qkv);
    cudaGetSymbolAddress((void**)&qk,  g_qk);
    cudaGetSymbolAddress((void**)&qr,  g_qr);
    cudaGetSymbolAddress((void**)&o,   g_o);
    cudaGetSymbolAddress((void**)&g,   g_g);

    // x = LN(emb[src] * sqrt(E))
    embed_ln_k<<<N_ROWS, 256>>>(src, emb, nin_s, nin_b, x);

    for (int l = 0; l < 4; l++) {
        const float* inW_l  = inW  + (size_t)l * QKV_DIM * E_DIM;
        const float* inB_l  = inB  + (size_t)l * QKV_DIM;
        const float* outW_l = outW + (size_t)l * E_DIM * E_DIM;
        const float* outB_l = outB + (size_t)l * E_DIM;
        const float* w1_l   = w1   + (size_t)l * FF_DIM * E_DIM;
        const float* b1_l   = b1   + (size_t)l * FF_DIM;
        const float* w2_l   = w2   + (size_t)l * E_DIM * FF_DIM;
        const float* b2_l   = b2   + (size_t)l * E_DIM;

        // h = LN1(x)
        layernorm_k<<<N_ROWS, 256>>>(x, ln1s + l * E_DIM, ln1b + l * E_DIM, h);

        // qkv = h @ inW^T + inB   [1024 x 1536]
        mma_gemm_k<0, 0><<<dim3(12, 8, 1), 256>>>(h, inW_l, inB_l, qkv,
            N_ROWS, QKV_DIM, E_DIM, E_DIM, E_DIM, QKV_DIM, 0, 0, 0, 0, 0, 0);

        // scores[bh] = Q @ K^T (batched z = b*8 + h), unscaled
        mma_gemm_k<0, 0><<<dim3(2, 2, N_BH), 256>>>(qkv, qkv + E_DIM, (const float*)0, qk,
            S_LEN, S_LEN, 64, QKV_DIM, QKV_DIM, S_LEN,
            S_LEN * QKV_DIM, 64,
            S_LEN * QKV_DIM, 64,
            8 * S_LEN * S_LEN, S_LEN * S_LEN);

        // qr[bh] = Q @ R^T  with R[p,d] = rel_table[p, h*64+d], p in [0,511)
        mma_gemm_k<0, 0><<<dim3(4, 2, N_BH), 256>>>(qkv, rel, (const float*)0, qr,
            S_LEN, 511, 64, QKV_DIM, E_DIM, 512,
            S_LEN * QKV_DIM, 64,
            0, 64,
            8 * S_LEN * 512, S_LEN * 512);

        // probs = softmax(scores/8 + qr_gather + triu_one_mask)
        softmax_k<<<dim3(S_LEN, N_BH), 256>>>(qk, qr);

        // o[bh] = probs @ V   (NN)
        mma_gemm_k<0, 1><<<dim3(1, 2, N_BH), 256>>>(qk, qkv + 2 * E_DIM, (const float*)0, o,
            S_LEN, 64, S_LEN, S_LEN, QKV_DIM, E_DIM,
            8 * S_LEN * S_LEN, S_LEN * S_LEN,
            S_LEN * QKV_DIM, 64,
            S_LEN * E_DIM, 64);

        // x += o @ outW^T + outB
        mma_gemm_k<1, 0><<<dim3(4, 8, 1), 256>>>(o, outW_l, outB_l, x,
            N_ROWS, E_DIM, E_DIM, E_DIM, E_DIM, E_DIM, 0, 0, 0, 0, 0, 0);

        // h = LN2(x)
        layernorm_k<<<N_ROWS, 256>>>(x, ln2s + l * E_DIM, ln2b + l * E_DIM, h);

        // g = gelu(h @ w1^T + b1)   [1024 x 2048]
        mma_gemm_k<2, 0><<<dim3(16, 8, 1), 256>>>(h, w1_l, b1_l, g,
            N_ROWS, FF_DIM, E_DIM, E_DIM, E_DIM, FF_DIM, 0, 0, 0, 0, 0, 0);

        // x += g @ w2^T + b2
        mma_gemm_k<1, 0><<<dim3(4, 8, 1), 256>>>(g, w2_l, b2_l, x,
            N_ROWS, E_DIM, FF_DIM, FF_DIM, FF_DIM, E_DIM, 0, 0, 0, 0, 0, 0);
    }

    // h = LN_final(x)
    layernorm_k<<<N_ROWS, 256>>>(x, nfs, nfb, h);

    // out = h @ dec_w^T + dec_b   [1024 x 32000]
    mma_gemm_k<0, 0><<<dim3(250, 8, 1), 256>>>(h, decW, decB, out,
        N_ROWS, V_DIM, E_DIM, E_DIM, E_DIM, V_DIM, 0, 0, 0, 0, 0, 0);
}